// round 13
// baseline (speedup 1.0000x reference)
#include <cuda_runtime.h>
#include <cuda_fp16.h>

#define BS   2048
#define HD   1024
#define NE   8
#define FF   512
#define TWOF 1024
#define EPSV 1e-9f

// ======================= device scratch =======================
__device__ int    g_expert_cnt[NE];
__device__ int    g_expert_tok[NE][BS];     // packed token*2 + k
__device__ float  g_expert_w[NE][BS];
__device__ int    g_sel[BS][2];
__device__ float  g_rw[BS][2];
__device__ int    g_flags[BS];              // bit0: valid0, bit1: mis0, bit2: valid1, bit3: mis1
__device__ int    g_arrive = 0;             // router-block arrival counter (self-resetting)
__device__ __half g_xr[BS][HD];             // fp16 x (4 MB)
__device__ __half g_W1T[NE][TWOF][HD];      // gate_up^T fp16 (16.8 MB)
__device__ __half g_W2T[NE][HD][FF];        // down^T fp16 (8.4 MB)
__device__ __half g_act[NE][BS][FF];        // silu(g)*u fp16 (16.8 MB)

// ======================= PTX helpers =======================
__device__ __forceinline__ unsigned smem_u32(const void* p) {
    unsigned a;
    asm("{ .reg .u64 t; cvta.to.shared.u64 t, %1; cvt.u32.u64 %0, t; }" : "=r"(a) : "l"(p));
    return a;
}
#define CP16(s, g) asm volatile("cp.async.cg.shared.global [%0], [%1], 16;" :: "r"(s), "l"(g))
#define CPCOMMIT() asm volatile("cp.async.commit_group;" ::: "memory")
#define CPWAIT(n)  asm volatile("cp.async.wait_group %0;" :: "n"(n) : "memory")
#define LDSM4(r0, r1, r2, r3, a) \
    asm volatile("ldmatrix.sync.aligned.m8n8.x4.shared.b16 {%0,%1,%2,%3}, [%4];" \
        : "=r"(r0), "=r"(r1), "=r"(r2), "=r"(r3) : "r"(a))
#define MMAH(c, a0, a1, a2, a3, b0, b1) \
    asm volatile("mma.sync.aligned.m16n8k16.row.col.f32.f16.f16.f32 " \
        "{%0,%1,%2,%3}, {%4,%5,%6,%7}, {%8,%9}, {%0,%1,%2,%3};" \
        : "+f"((c)[0]), "+f"((c)[1]), "+f"((c)[2]), "+f"((c)[3]) \
        : "r"(a0), "r"(a1), "r"(a2), "r"(a3), "r"(b0), "r"(b1))
#define REDV2(addr, a, b) \
    asm volatile("red.global.add.v2.f32 [%0], {%1, %2};" :: "l"(addr), "f"(a), "f"(b) : "memory")

// dynamic smem for MMA kernels
#define SMH_A(s) (1024 + (s) * 32768)
#define SMH_B(s) (1024 + (s) * 32768 + 16384)
#define SMH_BYTES (1024 + 3 * 32768)   // 99328

// ======================= K_fused: prep ∪ router ∪ (last-block) assign =======================
// Blocks [0,2048): W1 64x64 transpose tiles. [2048,3072): W2 tiles. [3072,3584): router.
#define ZO_F4 (BS * HD / 4)
#define PREP_BLOCKS 3072
#define ROUTER_BLOCKS 512
#define FUSED_BLOCKS (PREP_BLOCKS + ROUTER_BLOCKS)
__global__ void __launch_bounds__(256) k_fused(
    const float* __restrict__ gup, const float* __restrict__ down,
    const float* __restrict__ x, const float* __restrict__ gw,
    const int* __restrict__ tmod, const int* __restrict__ emod,
    float4* __restrict__ out)
{
    __shared__ float smf[NE * HD];   // router: sgw (32KB). prep: 64x72 half tile.
    __shared__ float part[8][NE];
    __shared__ int is_last;
    __shared__ int vcnt[NE], mcnt[NE], ecnt[NE], skip_s[NE];
    int b = blockIdx.x;
    int t = threadIdx.x;

    if (b >= PREP_BLOCKS) {
        // ---------------- router role ----------------
        int rb = b - PREP_BLOCKS;
        for (int i = t; i < NE * HD / 4; i += 256)
            *(float4*)&smf[i * 4] = ((const float4*)gw)[i];
        __syncthreads();

        int warp = t >> 5, lane = t & 31;
        int tok = rb * 4 + (warp >> 1);
        int hf = warp & 1;

        const float4* xr = (const float4*)(x + (size_t)tok * HD) + hf * 128;
        __half2* xo = (__half2*)&g_xr[tok][0] + hf * 256;
        float acc[NE];
        #pragma unroll
        for (int e = 0; e < NE; e++) acc[e] = 0.f;
        #pragma unroll
        for (int i = 0; i < 4; i++) {
            int q = lane + i * 32;
            float4 xv = xr[q];
            xo[q * 2 + 0] = __floats2half2_rn(xv.x, xv.y);
            xo[q * 2 + 1] = __floats2half2_rn(xv.z, xv.w);
            #pragma unroll
            for (int e = 0; e < NE; e++) {
                const float4 wv = *(const float4*)&smf[e * HD + (hf * 128 + q) * 4];
                acc[e] = fmaf(xv.x, wv.x, acc[e]);
                acc[e] = fmaf(xv.y, wv.y, acc[e]);
                acc[e] = fmaf(xv.z, wv.z, acc[e]);
                acc[e] = fmaf(xv.w, wv.w, acc[e]);
            }
        }
        #pragma unroll
        for (int e = 0; e < NE; e++) {
            #pragma unroll
            for (int o = 16; o > 0; o >>= 1) acc[e] += __shfl_xor_sync(0xffffffffu, acc[e], o);
        }
        if (lane == 0) {
            #pragma unroll
            for (int e = 0; e < NE; e++) part[warp][e] = acc[e];
        }
        __syncthreads();
        if (hf == 0 && lane == 0) {
            float p[NE];
            #pragma unroll
            for (int e = 0; e < NE; e++) p[e] = part[warp][e] + part[warp + 1][e];
            float m = p[0];
            #pragma unroll
            for (int e = 1; e < NE; e++) m = fmaxf(m, p[e]);
            float s = 0.f;
            #pragma unroll
            for (int e = 0; e < NE; e++) { p[e] = __expf(p[e] - m); s += p[e]; }
            float inv = 1.f / s;
            #pragma unroll
            for (int e = 0; e < NE; e++) p[e] *= inv;
            int i1 = 0; float m1 = p[0];
            #pragma unroll
            for (int e = 1; e < NE; e++) if (p[e] > m1) { m1 = p[e]; i1 = e; }
            int i2 = -1; float m2 = -1.f;
            #pragma unroll
            for (int e = 0; e < NE; e++) if (e != i1 && p[e] > m2) { m2 = p[e]; i2 = e; }
            float inv2 = 1.f / (m1 + m2);
            g_sel[tok][0] = i1; g_sel[tok][1] = i2;
            g_rw[tok][0] = m1 * inv2; g_rw[tok][1] = m2 * inv2;
            int tm = tmod[tok];
            int em0 = emod[i1], em1 = emod[i2];
            int fl = 0;
            if (tm != 0 && em0 != 0) { fl |= 1; if (tm * em0 == -1) fl |= 2; }
            if (tm != 0 && em1 != 0) { fl |= 4; if (tm * em1 == -1) fl |= 8; }
            g_flags[tok] = fl;
        }
        __syncthreads();
        // arrival: last router block performs the assign phase
        if (t == 0) {
            __threadfence();
            int old = atomicAdd(&g_arrive, 1);
            is_last = (old == ROUTER_BLOCKS - 1);
        }
        __syncthreads();
        if (!is_last) return;
        __threadfence();   // acquire all router blocks' writes

        // ---------------- assign phase (256 threads x 8 tokens) ----------------
        if (t < NE) { vcnt[t] = 0; mcnt[t] = 0; ecnt[t] = 0; }
        __syncthreads();
        int flg[8], s0a[8], s1a[8];
        float w0a[8], w1a[8];
        #pragma unroll
        for (int i = 0; i < 8; i++) {
            int tok = t + i * 256;
            flg[i] = g_flags[tok];
            s0a[i] = g_sel[tok][0]; s1a[i] = g_sel[tok][1];
            w0a[i] = g_rw[tok][0];  w1a[i] = g_rw[tok][1];
            if (flg[i] & 1) { atomicAdd(&vcnt[s0a[i]], 1); if (flg[i] & 2) atomicAdd(&mcnt[s0a[i]], 1); }
            if (flg[i] & 4) { atomicAdd(&vcnt[s1a[i]], 1); if (flg[i] & 8) atomicAdd(&mcnt[s1a[i]], 1); }
        }
        __syncthreads();
        if (t < NE) {
            int vc = vcnt[t], mc = mcnt[t];
            skip_s[t] = (vc > 0) && (mc == vc) && (emod[t] != 0);
        }
        __syncthreads();
        #pragma unroll
        for (int i = 0; i < 8; i++) {
            int tok = t + i * 256;
            float w0 = w0a[i], w1 = w1a[i];
            if (skip_s[s0a[i]]) w0 = 0.f;
            if (skip_s[s1a[i]]) w1 = 0.f;
            float sum = w0 + w1;
            if (sum > 0.f) { float inv = 1.f / fmaxf(sum, EPSV); w0 *= inv; w1 *= inv; }
            if (w0 > 0.f) {
                int p = atomicAdd(&ecnt[s0a[i]], 1);
                g_expert_tok[s0a[i]][p] = tok * 2;     g_expert_w[s0a[i]][p] = w0;
            }
            if (w1 > 0.f) {
                int p = atomicAdd(&ecnt[s1a[i]], 1);
                g_expert_tok[s1a[i]][p] = tok * 2 + 1; g_expert_w[s1a[i]][p] = w1;
            }
        }
        __syncthreads();
        if (t < NE) g_expert_cnt[t] = ecnt[t];
        if (t == 0) g_arrive = 0;   // reset for next graph replay
        return;
    }

    // ---------------- prep role ----------------
    __half* tileh = (__half*)smf;     // [64][72] transposed tile
    {
        unsigned zi = (unsigned)b * 256u + t;
        if (zi < ZO_F4) out[zi] = make_float4(0.f, 0.f, 0.f, 0.f);
    }
    const float* src; __half* dst;
    int kt, nt, src_ld, dst_ld;
    if (b < 2048) {
        int e = b >> 8, rem = b & 255;
        kt = (rem >> 4) * 64; nt = (rem & 15) * 64;
        src = gup + (size_t)e * HD * TWOF;  src_ld = TWOF;
        dst = &g_W1T[e][0][0];              dst_ld = HD;
    } else {
        int b2 = b - 2048;
        int e = b2 >> 7, rem = b2 & 127;
        kt = (rem >> 4) * 64; nt = (rem & 15) * 64;
        src = down + (size_t)e * FF * HD;   src_ld = HD;
        dst = &g_W2T[e][0][0];              dst_ld = FF;
    }
    int n4 = t & 15, r4 = t >> 4;
    float4 v[4];
    #pragma unroll
    for (int i = 0; i < 4; i++)
        v[i] = *(const float4*)(src + (size_t)(kt + r4 * 4 + i) * src_ld + nt + n4 * 4);
    const float* fv = (const float*)v;
    #pragma unroll
    for (int j = 0; j < 4; j++) {
        __half hh[4];
        #pragma unroll
        for (int i = 0; i < 4; i++) hh[i] = __float2half_rn(fv[i * 4 + j]);
        *(uint2*)&tileh[(n4 * 4 + j) * 72 + r4 * 4] = *(const uint2*)hh;
    }
    __syncthreads();
    #pragma unroll
    for (int j = 0; j < 2; j++) {
        int idx = t + j * 256;
        int rw = idx >> 3, u = idx & 7;
        uint4 val = *(const uint4*)&tileh[rw * 72 + u * 8];
        *(uint4*)(dst + (size_t)(nt + rw) * dst_ld + kt + u * 8) = val;
    }
}

// ======================= K_mma1: GEMM1 fp16 (fused gather) + SiLU*u, 3-stage ==============
__global__ void __launch_bounds__(256, 2) k_mma1() {
    int e = blockIdx.z;
    int count = g_expert_cnt[e];
    int m0 = blockIdx.y * 128;
    if (m0 >= count) return;
    int f0 = blockIdx.x * 64;

    extern __shared__ char sm[];
    unsigned sb = smem_u32(sm);
    int tid = threadIdx.x, lane = tid & 31, w = tid >> 5;
    int wm = w & 3, wn = w >> 2;

    int* ts = (int*)sm;
    if (tid < 128) {
        int s = m0 + tid;
        ts[tid] = (s < count) ? (g_expert_tok[e][s] >> 1) : 0;
    }
    __syncthreads();

    const __half* Xb = &g_xr[0][0];
    const __half* Wb = &g_W1T[e][0][0];

    unsigned ga_off[4]; const __half* gb[4]; unsigned soff[4];
    #pragma unroll
    for (int i = 0; i < 4; i++) {
        int idx = tid + i * 256;
        int r = idx >> 3, c = idx & 7;
        ga_off[i] = (unsigned)ts[r] * HD + c * 8;
        int bh = r >> 6, l = r & 63;
        int col = f0 + bh * 32 + (l & 31);
        int rowg = col + ((l & 32) ? 512 : 0);
        gb[i] = Wb + (size_t)rowg * HD + c * 8;
        soff[i] = r * 128 + ((c ^ (r & 7)) << 4);
    }

    float acc[2][8][4];
    #pragma unroll
    for (int h = 0; h < 2; h++)
        #pragma unroll
        for (int f = 0; f < 8; f++)
            #pragma unroll
            for (int q = 0; q < 4; q++) acc[h][f][q] = 0.f;

    int l7 = lane & 7;
    int rA0 = (((lane >> 3) & 1) << 3) + l7;
    int cA  = lane >> 4;
    int rB0 = ((lane >> 4) << 3) + l7;
    int cB  = (lane >> 3) & 1;
    unsigned arow = (unsigned)(wm * 32 + rA0) * 128;
    unsigned brow0 = (unsigned)(wn * 64 + rB0) * 128;

    const int NK = HD / 64;
    #pragma unroll
    for (int i = 0; i < 4; i++) {
        CP16(sb + SMH_A(0) + soff[i], Xb + ga_off[i]);
        CP16(sb + SMH_B(0) + soff[i], gb[i]);
    }
    CPCOMMIT();
    #pragma unroll
    for (int i = 0; i < 4; i++) {
        CP16(sb + SMH_A(1) + soff[i], Xb + ga_off[i] + 64);
        CP16(sb + SMH_B(1) + soff[i], gb[i] + 64);
    }
    CPCOMMIT();

    for (int kb = 0; kb < NK; kb++) {
        int s = kb % 3;
        if (kb >= NK - 1) { CPWAIT(0); } else { CPWAIT(1); }
        __syncthreads();
        if (kb + 2 < NK) {
            int ns = (kb + 2) % 3;
            #pragma unroll
            for (int i = 0; i < 4; i++) {
                CP16(sb + SMH_A(ns) + soff[i], Xb + ga_off[i] + (kb + 2) * 64);
                CP16(sb + SMH_B(ns) + soff[i], gb[i] + (kb + 2) * 64);
            }
            CPCOMMIT();
        }
        unsigned sA = sb + SMH_A(s) + arow;
        unsigned sB = sb + SMH_B(s) + brow0;
        #pragma unroll
        for (int kc = 0; kc < 4; kc++) {
            unsigned aoff = (unsigned)(((kc * 2 + cA) ^ l7) << 4);
            unsigned boff = (unsigned)(((kc * 2 + cB) ^ l7) << 4);
            unsigned a0, a1, a2, a3, a4, a5, a6, a7;
            LDSM4(a0, a1, a2, a3, sA + aoff);
            LDSM4(a4, a5, a6, a7, sA + 2048 + aoff);
            #pragma unroll
            for (int fg = 0; fg < 4; fg++) {
                unsigned b0, b1, b2, b3;
                LDSM4(b0, b1, b2, b3, sB + fg * 2048 + boff);
                MMAH(acc[0][2 * fg],     a0, a1, a2, a3, b0, b1);
                MMAH(acc[0][2 * fg + 1], a0, a1, a2, a3, b2, b3);
                MMAH(acc[1][2 * fg],     a4, a5, a6, a7, b0, b1);
                MMAH(acc[1][2 * fg + 1], a4, a5, a6, a7, b2, b3);
            }
        }
    }

    int p = lane & 3, rlo = lane >> 2;
    #pragma unroll
    for (int h = 0; h < 2; h++) {
        int slot0 = m0 + wm * 32 + h * 16 + rlo;
        int slot1 = slot0 + 8;
        #pragma unroll
        for (int f = 0; f < 4; f++) {
            int j = f0 + wn * 32 + f * 8 + 2 * p;
            if (slot0 < count) {
                float g0 = acc[h][f][0], g1 = acc[h][f][1];
                float u0 = acc[h][f + 4][0], u1 = acc[h][f + 4][1];
                float v0 = g0 / (1.f + __expf(-g0)) * u0;
                float v1 = g1 / (1.f + __expf(-g1)) * u1;
                *(__half2*)&g_act[e][slot0][j] = __floats2half2_rn(v0, v1);
            }
            if (slot1 < count) {
                float g0 = acc[h][f][2], g1 = acc[h][f][3];
                float u0 = acc[h][f + 4][2], u1 = acc[h][f + 4][3];
                float v0 = g0 / (1.f + __expf(-g0)) * u0;
                float v1 = g1 / (1.f + __expf(-g1)) * u1;
                *(__half2*)&g_act[e][slot1][j] = __floats2half2_rn(v0, v1);
            }
        }
    }
}

// ======================= K_mma2: GEMM2 fp16, 3-stage, v2-red accumulate ==========
__global__ void __launch_bounds__(256, 2) k_mma2(float* __restrict__ out) {
    int e = blockIdx.z;
    int count = g_expert_cnt[e];
    int m0 = blockIdx.y * 128;
    if (m0 >= count) return;
    int n0 = blockIdx.x * 128;

    extern __shared__ char sm[];
    unsigned sb = smem_u32(sm);
    int tid = threadIdx.x, lane = tid & 31, w = tid >> 5;
    int wm = w & 3, wn = w >> 2;

    int*   tsp = (int*)sm;
    float* tw  = (float*)(sm + 512);
    if (tid < 128) {
        int s = m0 + tid;
        tsp[tid] = (s < count) ? g_expert_tok[e][s] : -1;
        tw[tid]  = (s < count) ? g_expert_w[e][s] : 0.f;
    }
    __syncthreads();

    const __half* Ab = &g_act[e][m0][0];
    const __half* Wb = &g_W2T[e][n0][0];

    const __half* ga[4]; const __half* gb[4]; unsigned soff[4];
    #pragma unroll
    for (int i = 0; i < 4; i++) {
        int idx = tid + i * 256;
        int r = idx >> 3, c = idx & 7;
        ga[i] = Ab + (size_t)r * FF + c * 8;
        gb[i] = Wb + (size_t)r * FF + c * 8;
        soff[i] = r * 128 + ((c ^ (r & 7)) << 4);
    }

    float acc[2][8][4];
    #pragma unroll
    for (int h = 0; h < 2; h++)
        #pragma unroll
        for (int f = 0; f < 8; f++)
            #pragma unroll
            for (int q = 0; q < 4; q++) acc[h][f][q] = 0.f;

    int l7 = lane & 7;
    int rA0 = (((lane >> 3) & 1) << 3) + l7;
    int cA  = lane >> 4;
    int rB0 = ((lane >> 4) << 3) + l7;
    int cB  = (lane >> 3) & 1;
    unsigned arow = (unsigned)(wm * 32 + rA0) * 128;
    unsigned brow0 = (unsigned)(wn * 64 + rB0) * 128;

    const int NK = FF / 64;
    #pragma unroll
    for (int i = 0; i < 4; i++) {
        CP16(sb + SMH_A(0) + soff[i], ga[i]);
        CP16(sb + SMH_B(0) + soff[i], gb[i]);
    }
    CPCOMMIT();
    #pragma unroll
    for (int i = 0; i < 4; i++) {
        CP16(sb + SMH_A(1) + soff[i], ga[i] + 64);
        CP16(sb + SMH_B(1) + soff[i], gb[i] + 64);
    }
    CPCOMMIT();

    for (int kb = 0; kb < NK; kb++) {
        int s = kb % 3;
        if (kb >= NK - 1) { CPWAIT(0); } else { CPWAIT(1); }
        __syncthreads();
        if (kb + 2 < NK) {
            int ns = (kb + 2) % 3;
            #pragma unroll
            for (int i = 0; i < 4; i++) {
                CP16(sb + SMH_A(ns) + soff[i], ga[i] + (kb + 2) * 64);
                CP16(sb + SMH_B(ns) + soff[i], gb[i] + (kb + 2) * 64);
            }
            CPCOMMIT();
        }
        unsigned sA = sb + SMH_A(s) + arow;
        unsigned sB = sb + SMH_B(s) + brow0;
        #pragma unroll
        for (int kc = 0; kc < 4; kc++) {
            unsigned aoff = (unsigned)(((kc * 2 + cA) ^ l7) << 4);
            unsigned boff = (unsigned)(((kc * 2 + cB) ^ l7) << 4);
            unsigned a0, a1, a2, a3, a4, a5, a6, a7;
            LDSM4(a0, a1, a2, a3, sA + aoff);
            LDSM4(a4, a5, a6, a7, sA + 2048 + aoff);
            #pragma unroll
            for (int fg = 0; fg < 4; fg++) {
                unsigned b0, b1, b2, b3;
                LDSM4(b0, b1, b2, b3, sB + fg * 2048 + boff);
                MMAH(acc[0][2 * fg],     a0, a1, a2, a3, b0, b1);
                MMAH(acc[0][2 * fg + 1], a0, a1, a2, a3, b2, b3);
                MMAH(acc[1][2 * fg],     a4, a5, a6, a7, b0, b1);
                MMAH(acc[1][2 * fg + 1], a4, a5, a6, a7, b2, b3);
            }
        }
    }

    // epilogue: weighted v2 reductions into out (pre-zeroed; <=2 adds/address)
    int p = lane & 3, rlo = lane >> 2;
    #pragma unroll
    for (int h = 0; h < 2; h++) {
        int r0i = wm * 32 + h * 16 + rlo;
        int r1i = r0i + 8;
        int pk0 = tsp[r0i], pk1 = tsp[r1i];
        float wt0 = tw[r0i], wt1 = tw[r1i];
        #pragma unroll
        for (int f = 0; f < 8; f++) {
            int j = n0 + wn * 64 + f * 8 + 2 * p;
            if (pk0 >= 0) {
                float* dst = out + (size_t)(pk0 >> 1) * HD + j;
                REDV2(dst, acc[h][f][0] * wt0, acc[h][f][1] * wt0);
            }
            if (pk1 >= 0) {
                float* dst = out + (size_t)(pk1 >> 1) * HD + j;
                REDV2(dst, acc[h][f][2] * wt1, acc[h][f][3] * wt1);
            }
        }
    }
}

// ======================= launch =======================
extern "C" void kernel_launch(void* const* d_in, const int* in_sizes, int n_in,
                              void* d_out, int out_size)
{
    const float* x    = (const float*)d_in[0];
    const float* gw   = (const float*)d_in[1];
    const float* gup  = (const float*)d_in[2];
    const float* down = (const float*)d_in[3];
    const int*   tmod = (const int*)d_in[4];
    const int*   emod = (const int*)d_in[5];
    float* out = (float*)d_out;

    cudaFuncSetAttribute(k_mma1, cudaFuncAttributeMaxDynamicSharedMemorySize, SMH_BYTES);
    cudaFuncSetAttribute(k_mma2, cudaFuncAttributeMaxDynamicSharedMemorySize, SMH_BYTES);

    k_fused<<<FUSED_BLOCKS, 256>>>(gup, down, x, gw, tmod, emod, (float4*)out);
    k_mma1<<<dim3(8, 16, NE), 256, SMH_BYTES>>>();
    k_mma2<<<dim3(8, 16, NE), 256, SMH_BYTES>>>(out);
}

// round 14
// speedup vs baseline: 1.0852x; 1.0852x over previous
#include <cuda_runtime.h>
#include <cuda_fp16.h>

#define BS   2048
#define HD   1024
#define NE   8
#define FF   512
#define TWOF 1024
#define EPSV 1e-9f

// ======================= device scratch =======================
__device__ int    g_expert_cnt[NE];
__device__ int    g_expert_tok[NE][BS];     // packed token*2 + k
__device__ float  g_expert_w[NE][BS];
__device__ int    g_sel[BS][2];
__device__ float  g_rw[BS][2];
__device__ int    g_flags[BS];              // bit0: valid0, bit1: mis0, bit2: valid1, bit3: mis1
__device__ __half g_xr[BS][HD];             // fp16 x (4 MB)
__device__ __half g_W1T[NE][TWOF][HD];      // gate_up^T fp16 (16.8 MB)
__device__ __half g_W2T[NE][HD][FF];        // down^T fp16 (8.4 MB)
__device__ __half g_act[NE][BS][FF];        // silu(g)*u fp16 (16.8 MB)

// ======================= PTX helpers =======================
__device__ __forceinline__ unsigned smem_u32(const void* p) {
    unsigned a;
    asm("{ .reg .u64 t; cvta.to.shared.u64 t, %1; cvt.u32.u64 %0, t; }" : "=r"(a) : "l"(p));
    return a;
}
#define CP16(s, g) asm volatile("cp.async.cg.shared.global [%0], [%1], 16;" :: "r"(s), "l"(g))
#define CPCOMMIT() asm volatile("cp.async.commit_group;" ::: "memory")
#define CPWAIT(n)  asm volatile("cp.async.wait_group %0;" :: "n"(n) : "memory")
#define LDSM4(r0, r1, r2, r3, a) \
    asm volatile("ldmatrix.sync.aligned.m8n8.x4.shared.b16 {%0,%1,%2,%3}, [%4];" \
        : "=r"(r0), "=r"(r1), "=r"(r2), "=r"(r3) : "r"(a))
#define MMAH(c, a0, a1, a2, a3, b0, b1) \
    asm volatile("mma.sync.aligned.m16n8k16.row.col.f32.f16.f16.f32 " \
        "{%0,%1,%2,%3}, {%4,%5,%6,%7}, {%8,%9}, {%0,%1,%2,%3};" \
        : "+f"((c)[0]), "+f"((c)[1]), "+f"((c)[2]), "+f"((c)[3]) \
        : "r"(a0), "r"(a1), "r"(a2), "r"(a3), "r"(b0), "r"(b1))
#define REDV2(addr, a, b) \
    asm volatile("red.global.add.v2.f32 [%0], {%1, %2};" :: "l"(addr), "f"(a), "f"(b) : "memory")

// dynamic smem for MMA kernels
#define SMH_A(s) (1024 + (s) * 32768)
#define SMH_B(s) (1024 + (s) * 32768 + 16384)
#define SMH_BYTES (1024 + 3 * 32768)   // 99328

// ======================= K_fused: router (blocks 0-511) ∪ prep (blocks 512-3583) ==============
// Router first so it overlaps prep's memory waves instead of trailing them.
#define ZO_F4 (BS * HD / 4)
#define ROUTER_BLOCKS 512
#define PREP_BLOCKS 3072
#define FUSED_BLOCKS (ROUTER_BLOCKS + PREP_BLOCKS)
__global__ void __launch_bounds__(256, 6) k_fused(
    const float* __restrict__ gup, const float* __restrict__ down,
    const float* __restrict__ x, const float* __restrict__ gw,
    const int* __restrict__ tmod, const int* __restrict__ emod,
    float4* __restrict__ out)
{
    __shared__ float smf[NE * HD];   // router: sgw (32KB). prep: 64x72 half tile.
    __shared__ float part[8][NE];
    int b = blockIdx.x;
    int t = threadIdx.x;

    if (b < ROUTER_BLOCKS) {
        // ---------------- router role ----------------
        for (int i = t; i < NE * HD / 4; i += 256)
            *(float4*)&smf[i * 4] = ((const float4*)gw)[i];
        __syncthreads();

        int warp = t >> 5, lane = t & 31;
        int tok = b * 4 + (warp >> 1);
        int hf = warp & 1;

        const float4* xr = (const float4*)(x + (size_t)tok * HD) + hf * 128;
        __half2* xo = (__half2*)&g_xr[tok][0] + hf * 256;
        float acc[NE];
        #pragma unroll
        for (int e = 0; e < NE; e++) acc[e] = 0.f;
        #pragma unroll
        for (int i = 0; i < 4; i++) {
            int q = lane + i * 32;
            float4 xv = xr[q];
            xo[q * 2 + 0] = __floats2half2_rn(xv.x, xv.y);
            xo[q * 2 + 1] = __floats2half2_rn(xv.z, xv.w);
            #pragma unroll
            for (int e = 0; e < NE; e++) {
                const float4 wv = *(const float4*)&smf[e * HD + (hf * 128 + q) * 4];
                acc[e] = fmaf(xv.x, wv.x, acc[e]);
                acc[e] = fmaf(xv.y, wv.y, acc[e]);
                acc[e] = fmaf(xv.z, wv.z, acc[e]);
                acc[e] = fmaf(xv.w, wv.w, acc[e]);
            }
        }
        #pragma unroll
        for (int e = 0; e < NE; e++) {
            #pragma unroll
            for (int o = 16; o > 0; o >>= 1) acc[e] += __shfl_xor_sync(0xffffffffu, acc[e], o);
        }
        if (lane == 0) {
            #pragma unroll
            for (int e = 0; e < NE; e++) part[warp][e] = acc[e];
        }
        __syncthreads();
        if (hf == 0 && lane == 0) {
            float p[NE];
            #pragma unroll
            for (int e = 0; e < NE; e++) p[e] = part[warp][e] + part[warp + 1][e];
            float m = p[0];
            #pragma unroll
            for (int e = 1; e < NE; e++) m = fmaxf(m, p[e]);
            float s = 0.f;
            #pragma unroll
            for (int e = 0; e < NE; e++) { p[e] = __expf(p[e] - m); s += p[e]; }
            float inv = 1.f / s;
            #pragma unroll
            for (int e = 0; e < NE; e++) p[e] *= inv;
            int i1 = 0; float m1 = p[0];
            #pragma unroll
            for (int e = 1; e < NE; e++) if (p[e] > m1) { m1 = p[e]; i1 = e; }
            int i2 = -1; float m2 = -1.f;
            #pragma unroll
            for (int e = 0; e < NE; e++) if (e != i1 && p[e] > m2) { m2 = p[e]; i2 = e; }
            float inv2 = 1.f / (m1 + m2);
            g_sel[tok][0] = i1; g_sel[tok][1] = i2;
            g_rw[tok][0] = m1 * inv2; g_rw[tok][1] = m2 * inv2;
            int tm = tmod[tok];
            int em0 = emod[i1], em1 = emod[i2];
            int fl = 0;
            if (tm != 0 && em0 != 0) { fl |= 1; if (tm * em0 == -1) fl |= 2; }
            if (tm != 0 && em1 != 0) { fl |= 4; if (tm * em1 == -1) fl |= 8; }
            g_flags[tok] = fl;
        }
        return;
    }

    // ---------------- prep role ----------------
    int pb = b - ROUTER_BLOCKS;        // 0 .. 3071
    __half* tileh = (__half*)smf;      // [64][72] transposed tile
    {
        unsigned zi = (unsigned)pb * 256u + t;
        if (zi < ZO_F4) out[zi] = make_float4(0.f, 0.f, 0.f, 0.f);
    }
    const float* src; __half* dst;
    int kt, nt, src_ld, dst_ld;
    if (pb < 2048) {
        int e = pb >> 8, rem = pb & 255;
        kt = (rem >> 4) * 64; nt = (rem & 15) * 64;
        src = gup + (size_t)e * HD * TWOF;  src_ld = TWOF;
        dst = &g_W1T[e][0][0];              dst_ld = HD;
    } else {
        int b2 = pb - 2048;
        int e = b2 >> 7, rem = b2 & 127;
        kt = (rem >> 4) * 64; nt = (rem & 15) * 64;
        src = down + (size_t)e * FF * HD;   src_ld = HD;
        dst = &g_W2T[e][0][0];              dst_ld = FF;
    }
    int n4 = t & 15, r4 = t >> 4;
    float4 v[4];
    #pragma unroll
    for (int i = 0; i < 4; i++)
        v[i] = *(const float4*)(src + (size_t)(kt + r4 * 4 + i) * src_ld + nt + n4 * 4);
    const float* fv = (const float*)v;
    #pragma unroll
    for (int j = 0; j < 4; j++) {
        __half hh[4];
        #pragma unroll
        for (int i = 0; i < 4; i++) hh[i] = __float2half_rn(fv[i * 4 + j]);
        *(uint2*)&tileh[(n4 * 4 + j) * 72 + r4 * 4] = *(const uint2*)hh;
    }
    __syncthreads();
    #pragma unroll
    for (int j = 0; j < 2; j++) {
        int idx = t + j * 256;
        int rw = idx >> 3, u = idx & 7;
        uint4 val = *(const uint4*)&tileh[rw * 72 + u * 8];
        *(uint4*)(dst + (size_t)(nt + rw) * dst_ld + kt + u * 8) = val;
    }
}

// ======================= K_assign2: single block — counts, skip, renorm, compaction ==========
__global__ void __launch_bounds__(512) k_assign2(const int* __restrict__ emod) {
    __shared__ int vcnt[NE], mcnt[NE], ecnt[NE];
    __shared__ int skip_s[NE];
    int t = threadIdx.x;
    if (t < NE) { vcnt[t] = 0; mcnt[t] = 0; ecnt[t] = 0; }
    __syncthreads();

    int flg[4], sel0[4], sel1[4];
    float w0a[4], w1a[4];
    #pragma unroll
    for (int i = 0; i < 4; i++) {
        int tok = t + i * 512;
        flg[i]  = g_flags[tok];
        sel0[i] = g_sel[tok][0]; sel1[i] = g_sel[tok][1];
        w0a[i]  = g_rw[tok][0];  w1a[i]  = g_rw[tok][1];
        if (flg[i] & 1) { atomicAdd(&vcnt[sel0[i]], 1); if (flg[i] & 2) atomicAdd(&mcnt[sel0[i]], 1); }
        if (flg[i] & 4) { atomicAdd(&vcnt[sel1[i]], 1); if (flg[i] & 8) atomicAdd(&mcnt[sel1[i]], 1); }
    }
    __syncthreads();
    if (t < NE) {
        int vc = vcnt[t], mc = mcnt[t];
        skip_s[t] = (vc > 0) && (mc == vc) && (emod[t] != 0);
    }
    __syncthreads();

    #pragma unroll
    for (int i = 0; i < 4; i++) {
        int tok = t + i * 512;
        float w0 = w0a[i], w1 = w1a[i];
        if (skip_s[sel0[i]]) w0 = 0.f;
        if (skip_s[sel1[i]]) w1 = 0.f;
        float sum = w0 + w1;
        if (sum > 0.f) { float inv = 1.f / fmaxf(sum, EPSV); w0 *= inv; w1 *= inv; }
        if (w0 > 0.f) {
            int p = atomicAdd(&ecnt[sel0[i]], 1);
            g_expert_tok[sel0[i]][p] = tok * 2;     g_expert_w[sel0[i]][p] = w0;
        }
        if (w1 > 0.f) {
            int p = atomicAdd(&ecnt[sel1[i]], 1);
            g_expert_tok[sel1[i]][p] = tok * 2 + 1; g_expert_w[sel1[i]][p] = w1;
        }
    }
    __syncthreads();
    if (t < NE) g_expert_cnt[t] = ecnt[t];
}

// ======================= K_mma1: GEMM1 fp16 (fused gather) + SiLU*u, 3-stage ==============
__global__ void __launch_bounds__(256, 2) k_mma1() {
    int e = blockIdx.z;
    int count = g_expert_cnt[e];
    int m0 = blockIdx.y * 128;
    if (m0 >= count) return;
    int f0 = blockIdx.x * 64;

    extern __shared__ char sm[];
    unsigned sb = smem_u32(sm);
    int tid = threadIdx.x, lane = tid & 31, w = tid >> 5;
    int wm = w & 3, wn = w >> 2;

    int* ts = (int*)sm;
    if (tid < 128) {
        int s = m0 + tid;
        ts[tid] = (s < count) ? (g_expert_tok[e][s] >> 1) : 0;
    }
    __syncthreads();

    const __half* Xb = &g_xr[0][0];
    const __half* Wb = &g_W1T[e][0][0];

    unsigned ga_off[4]; const __half* gb[4]; unsigned soff[4];
    #pragma unroll
    for (int i = 0; i < 4; i++) {
        int idx = tid + i * 256;
        int r = idx >> 3, c = idx & 7;
        ga_off[i] = (unsigned)ts[r] * HD + c * 8;
        int bh = r >> 6, l = r & 63;
        int col = f0 + bh * 32 + (l & 31);
        int rowg = col + ((l & 32) ? 512 : 0);
        gb[i] = Wb + (size_t)rowg * HD + c * 8;
        soff[i] = r * 128 + ((c ^ (r & 7)) << 4);
    }

    float acc[2][8][4];
    #pragma unroll
    for (int h = 0; h < 2; h++)
        #pragma unroll
        for (int f = 0; f < 8; f++)
            #pragma unroll
            for (int q = 0; q < 4; q++) acc[h][f][q] = 0.f;

    int l7 = lane & 7;
    int rA0 = (((lane >> 3) & 1) << 3) + l7;
    int cA  = lane >> 4;
    int rB0 = ((lane >> 4) << 3) + l7;
    int cB  = (lane >> 3) & 1;
    unsigned arow = (unsigned)(wm * 32 + rA0) * 128;
    unsigned brow0 = (unsigned)(wn * 64 + rB0) * 128;

    const int NK = HD / 64;
    #pragma unroll
    for (int i = 0; i < 4; i++) {
        CP16(sb + SMH_A(0) + soff[i], Xb + ga_off[i]);
        CP16(sb + SMH_B(0) + soff[i], gb[i]);
    }
    CPCOMMIT();
    #pragma unroll
    for (int i = 0; i < 4; i++) {
        CP16(sb + SMH_A(1) + soff[i], Xb + ga_off[i] + 64);
        CP16(sb + SMH_B(1) + soff[i], gb[i] + 64);
    }
    CPCOMMIT();

    for (int kb = 0; kb < NK; kb++) {
        int s = kb % 3;
        if (kb >= NK - 1) { CPWAIT(0); } else { CPWAIT(1); }
        __syncthreads();
        if (kb + 2 < NK) {
            int ns = (kb + 2) % 3;
            #pragma unroll
            for (int i = 0; i < 4; i++) {
                CP16(sb + SMH_A(ns) + soff[i], Xb + ga_off[i] + (kb + 2) * 64);
                CP16(sb + SMH_B(ns) + soff[i], gb[i] + (kb + 2) * 64);
            }
            CPCOMMIT();
        }
        unsigned sA = sb + SMH_A(s) + arow;
        unsigned sB = sb + SMH_B(s) + brow0;
        #pragma unroll
        for (int kc = 0; kc < 4; kc++) {
            unsigned aoff = (unsigned)(((kc * 2 + cA) ^ l7) << 4);
            unsigned boff = (unsigned)(((kc * 2 + cB) ^ l7) << 4);
            unsigned a0, a1, a2, a3, a4, a5, a6, a7;
            LDSM4(a0, a1, a2, a3, sA + aoff);
            LDSM4(a4, a5, a6, a7, sA + 2048 + aoff);
            #pragma unroll
            for (int fg = 0; fg < 4; fg++) {
                unsigned b0, b1, b2, b3;
                LDSM4(b0, b1, b2, b3, sB + fg * 2048 + boff);
                MMAH(acc[0][2 * fg],     a0, a1, a2, a3, b0, b1);
                MMAH(acc[0][2 * fg + 1], a0, a1, a2, a3, b2, b3);
                MMAH(acc[1][2 * fg],     a4, a5, a6, a7, b0, b1);
                MMAH(acc[1][2 * fg + 1], a4, a5, a6, a7, b2, b3);
            }
        }
    }

    int p = lane & 3, rlo = lane >> 2;
    #pragma unroll
    for (int h = 0; h < 2; h++) {
        int slot0 = m0 + wm * 32 + h * 16 + rlo;
        int slot1 = slot0 + 8;
        #pragma unroll
        for (int f = 0; f < 4; f++) {
            int j = f0 + wn * 32 + f * 8 + 2 * p;
            if (slot0 < count) {
                float g0 = acc[h][f][0], g1 = acc[h][f][1];
                float u0 = acc[h][f + 4][0], u1 = acc[h][f + 4][1];
                float v0 = g0 / (1.f + __expf(-g0)) * u0;
                float v1 = g1 / (1.f + __expf(-g1)) * u1;
                *(__half2*)&g_act[e][slot0][j] = __floats2half2_rn(v0, v1);
            }
            if (slot1 < count) {
                float g0 = acc[h][f][2], g1 = acc[h][f][3];
                float u0 = acc[h][f + 4][2], u1 = acc[h][f + 4][3];
                float v0 = g0 / (1.f + __expf(-g0)) * u0;
                float v1 = g1 / (1.f + __expf(-g1)) * u1;
                *(__half2*)&g_act[e][slot1][j] = __floats2half2_rn(v0, v1);
            }
        }
    }
}

// ======================= K_mma2: GEMM2 fp16, 3-stage, v2-red accumulate ==========
__global__ void __launch_bounds__(256, 2) k_mma2(float* __restrict__ out) {
    int e = blockIdx.z;
    int count = g_expert_cnt[e];
    int m0 = blockIdx.y * 128;
    if (m0 >= count) return;
    int n0 = blockIdx.x * 128;

    extern __shared__ char sm[];
    unsigned sb = smem_u32(sm);
    int tid = threadIdx.x, lane = tid & 31, w = tid >> 5;
    int wm = w & 3, wn = w >> 2;

    int*   tsp = (int*)sm;
    float* tw  = (float*)(sm + 512);
    if (tid < 128) {
        int s = m0 + tid;
        tsp[tid] = (s < count) ? g_expert_tok[e][s] : -1;
        tw[tid]  = (s < count) ? g_expert_w[e][s] : 0.f;
    }
    __syncthreads();

    const __half* Ab = &g_act[e][m0][0];
    const __half* Wb = &g_W2T[e][n0][0];

    const __half* ga[4]; const __half* gb[4]; unsigned soff[4];
    #pragma unroll
    for (int i = 0; i < 4; i++) {
        int idx = tid + i * 256;
        int r = idx >> 3, c = idx & 7;
        ga[i] = Ab + (size_t)r * FF + c * 8;
        gb[i] = Wb + (size_t)r * FF + c * 8;
        soff[i] = r * 128 + ((c ^ (r & 7)) << 4);
    }

    float acc[2][8][4];
    #pragma unroll
    for (int h = 0; h < 2; h++)
        #pragma unroll
        for (int f = 0; f < 8; f++)
            #pragma unroll
            for (int q = 0; q < 4; q++) acc[h][f][q] = 0.f;

    int l7 = lane & 7;
    int rA0 = (((lane >> 3) & 1) << 3) + l7;
    int cA  = lane >> 4;
    int rB0 = ((lane >> 4) << 3) + l7;
    int cB  = (lane >> 3) & 1;
    unsigned arow = (unsigned)(wm * 32 + rA0) * 128;
    unsigned brow0 = (unsigned)(wn * 64 + rB0) * 128;

    const int NK = FF / 64;
    #pragma unroll
    for (int i = 0; i < 4; i++) {
        CP16(sb + SMH_A(0) + soff[i], ga[i]);
        CP16(sb + SMH_B(0) + soff[i], gb[i]);
    }
    CPCOMMIT();
    #pragma unroll
    for (int i = 0; i < 4; i++) {
        CP16(sb + SMH_A(1) + soff[i], ga[i] + 64);
        CP16(sb + SMH_B(1) + soff[i], gb[i] + 64);
    }
    CPCOMMIT();

    for (int kb = 0; kb < NK; kb++) {
        int s = kb % 3;
        if (kb >= NK - 1) { CPWAIT(0); } else { CPWAIT(1); }
        __syncthreads();
        if (kb + 2 < NK) {
            int ns = (kb + 2) % 3;
            #pragma unroll
            for (int i = 0; i < 4; i++) {
                CP16(sb + SMH_A(ns) + soff[i], ga[i] + (kb + 2) * 64);
                CP16(sb + SMH_B(ns) + soff[i], gb[i] + (kb + 2) * 64);
            }
            CPCOMMIT();
        }
        unsigned sA = sb + SMH_A(s) + arow;
        unsigned sB = sb + SMH_B(s) + brow0;
        #pragma unroll
        for (int kc = 0; kc < 4; kc++) {
            unsigned aoff = (unsigned)(((kc * 2 + cA) ^ l7) << 4);
            unsigned boff = (unsigned)(((kc * 2 + cB) ^ l7) << 4);
            unsigned a0, a1, a2, a3, a4, a5, a6, a7;
            LDSM4(a0, a1, a2, a3, sA + aoff);
            LDSM4(a4, a5, a6, a7, sA + 2048 + aoff);
            #pragma unroll
            for (int fg = 0; fg < 4; fg++) {
                unsigned b0, b1, b2, b3;
                LDSM4(b0, b1, b2, b3, sB + fg * 2048 + boff);
                MMAH(acc[0][2 * fg],     a0, a1, a2, a3, b0, b1);
                MMAH(acc[0][2 * fg + 1], a0, a1, a2, a3, b2, b3);
                MMAH(acc[1][2 * fg],     a4, a5, a6, a7, b0, b1);
                MMAH(acc[1][2 * fg + 1], a4, a5, a6, a7, b2, b3);
            }
        }
    }

    // epilogue: weighted v2 reductions into out (pre-zeroed; <=2 adds/address)
    int p = lane & 3, rlo = lane >> 2;
    #pragma unroll
    for (int h = 0; h < 2; h++) {
        int r0i = wm * 32 + h * 16 + rlo;
        int r1i = r0i + 8;
        int pk0 = tsp[r0i], pk1 = tsp[r1i];
        float wt0 = tw[r0i], wt1 = tw[r1i];
        #pragma unroll
        for (int f = 0; f < 8; f++) {
            int j = n0 + wn * 64 + f * 8 + 2 * p;
            if (pk0 >= 0) {
                float* dst = out + (size_t)(pk0 >> 1) * HD + j;
                REDV2(dst, acc[h][f][0] * wt0, acc[h][f][1] * wt0);
            }
            if (pk1 >= 0) {
                float* dst = out + (size_t)(pk1 >> 1) * HD + j;
                REDV2(dst, acc[h][f][2] * wt1, acc[h][f][3] * wt1);
            }
        }
    }
}

// ======================= launch =======================
extern "C" void kernel_launch(void* const* d_in, const int* in_sizes, int n_in,
                              void* d_out, int out_size)
{
    const float* x    = (const float*)d_in[0];
    const float* gw   = (const float*)d_in[1];
    const float* gup  = (const float*)d_in[2];
    const float* down = (const float*)d_in[3];
    const int*   tmod = (const int*)d_in[4];
    const int*   emod = (const int*)d_in[5];
    float* out = (float*)d_out;

    cudaFuncSetAttribute(k_mma1, cudaFuncAttributeMaxDynamicSharedMemorySize, SMH_BYTES);
    cudaFuncSetAttribute(k_mma2, cudaFuncAttributeMaxDynamicSharedMemorySize, SMH_BYTES);

    k_fused<<<FUSED_BLOCKS, 256>>>(gup, down, x, gw, tmod, emod, (float4*)out);
    k_assign2<<<1, 512>>>(emod);
    k_mma1<<<dim3(8, 16, NE), 256, SMH_BYTES>>>();
    k_mma2<<<dim3(8, 16, NE), 256, SMH_BYTES>>>(out);
}

// round 16
// speedup vs baseline: 1.0911x; 1.0054x over previous
#include <cuda_runtime.h>
#include <cuda_fp16.h>

#define BS   2048
#define HD   1024
#define NE   8
#define FF   512
#define TWOF 1024
#define EPSV 1e-9f

// ======================= device scratch =======================
__device__ int    g_expert_cnt[NE];
__device__ int    g_expert_tok[NE][BS];     // packed token*2 + k
__device__ float  g_expert_w[NE][BS];
__device__ int    g_sel[BS][2];
__device__ float  g_rw[BS][2];
__device__ int    g_flags[BS];              // bit0: valid0, bit1: mis0, bit2: valid1, bit3: mis1
__device__ __half g_xr[BS][HD];             // fp16 x (4 MB)
__device__ __half g_W1T[NE][TWOF][HD];      // gate_up^T fp16 (16.8 MB)
__device__ __half g_W2T[NE][HD][FF];        // down^T fp16 (8.4 MB)
__device__ __half g_act[NE][BS][FF];        // silu(g)*u fp16 (16.8 MB)

// ======================= PTX helpers =======================
__device__ __forceinline__ unsigned smem_u32(const void* p) {
    unsigned a;
    asm("{ .reg .u64 t; cvta.to.shared.u64 t, %1; cvt.u32.u64 %0, t; }" : "=r"(a) : "l"(p));
    return a;
}
#define CP16(s, g) asm volatile("cp.async.cg.shared.global [%0], [%1], 16;" :: "r"(s), "l"(g))
#define CPCOMMIT() asm volatile("cp.async.commit_group;" ::: "memory")
#define CPWAIT(n)  asm volatile("cp.async.wait_group %0;" :: "n"(n) : "memory")
#define LDSM4(r0, r1, r2, r3, a) \
    asm volatile("ldmatrix.sync.aligned.m8n8.x4.shared.b16 {%0,%1,%2,%3}, [%4];" \
        : "=r"(r0), "=r"(r1), "=r"(r2), "=r"(r3) : "r"(a))
#define MMAH(c, a0, a1, a2, a3, b0, b1) \
    asm volatile("mma.sync.aligned.m16n8k16.row.col.f32.f16.f16.f32 " \
        "{%0,%1,%2,%3}, {%4,%5,%6,%7}, {%8,%9}, {%0,%1,%2,%3};" \
        : "+f"((c)[0]), "+f"((c)[1]), "+f"((c)[2]), "+f"((c)[3]) \
        : "r"(a0), "r"(a1), "r"(a2), "r"(a3), "r"(b0), "r"(b1))
#define REDV2(addr, a, b) \
    asm volatile("red.global.add.v2.f32 [%0], {%1, %2};" :: "l"(addr), "f"(a), "f"(b) : "memory")

// dynamic smem for MMA kernels
#define SMH_A(s) (1024 + (s) * 32768)
#define SMH_B(s) (1024 + (s) * 32768 + 16384)
#define SMH_BYTES (1024 + 3 * 32768)   // 99328

// ======================= K_fused: router (blocks 0-511) ∪ prep (blocks 512-3583) ==============
#define ROUTER_BLOCKS 512
#define PREP_BLOCKS 3072
#define FUSED_BLOCKS (ROUTER_BLOCKS + PREP_BLOCKS)
__global__ void __launch_bounds__(256, 6) k_fused(
    const float* __restrict__ gup, const float* __restrict__ down,
    const float* __restrict__ x, const float* __restrict__ gw,
    const int* __restrict__ tmod, const int* __restrict__ emod)
{
    __shared__ float smf[NE * HD];   // router: sgw (32KB). prep: 64x72 half tile.
    __shared__ float part[8][NE];
    int b = blockIdx.x;
    int t = threadIdx.x;

    if (b < ROUTER_BLOCKS) {
        // ---------------- router role ----------------
        for (int i = t; i < NE * HD / 4; i += 256)
            *(float4*)&smf[i * 4] = ((const float4*)gw)[i];
        __syncthreads();

        int warp = t >> 5, lane = t & 31;
        int tok = b * 4 + (warp >> 1);
        int hf = warp & 1;

        const float4* xr = (const float4*)(x + (size_t)tok * HD) + hf * 128;
        __half2* xo = (__half2*)&g_xr[tok][0] + hf * 256;
        float acc[NE];
        #pragma unroll
        for (int e = 0; e < NE; e++) acc[e] = 0.f;
        #pragma unroll
        for (int i = 0; i < 4; i++) {
            int q = lane + i * 32;
            float4 xv = xr[q];
            xo[q * 2 + 0] = __floats2half2_rn(xv.x, xv.y);
            xo[q * 2 + 1] = __floats2half2_rn(xv.z, xv.w);
            #pragma unroll
            for (int e = 0; e < NE; e++) {
                const float4 wv = *(const float4*)&smf[e * HD + (hf * 128 + q) * 4];
                acc[e] = fmaf(xv.x, wv.x, acc[e]);
                acc[e] = fmaf(xv.y, wv.y, acc[e]);
                acc[e] = fmaf(xv.z, wv.z, acc[e]);
                acc[e] = fmaf(xv.w, wv.w, acc[e]);
            }
        }
        #pragma unroll
        for (int e = 0; e < NE; e++) {
            #pragma unroll
            for (int o = 16; o > 0; o >>= 1) acc[e] += __shfl_xor_sync(0xffffffffu, acc[e], o);
        }
        if (lane == 0) {
            #pragma unroll
            for (int e = 0; e < NE; e++) part[warp][e] = acc[e];
        }
        __syncthreads();
        if (hf == 0 && lane == 0) {
            float p[NE];
            #pragma unroll
            for (int e = 0; e < NE; e++) p[e] = part[warp][e] + part[warp + 1][e];
            float m = p[0];
            #pragma unroll
            for (int e = 1; e < NE; e++) m = fmaxf(m, p[e]);
            float s = 0.f;
            #pragma unroll
            for (int e = 0; e < NE; e++) { p[e] = __expf(p[e] - m); s += p[e]; }
            float inv = 1.f / s;
            #pragma unroll
            for (int e = 0; e < NE; e++) p[e] *= inv;
            int i1 = 0; float m1 = p[0];
            #pragma unroll
            for (int e = 1; e < NE; e++) if (p[e] > m1) { m1 = p[e]; i1 = e; }
            int i2 = -1; float m2 = -1.f;
            #pragma unroll
            for (int e = 0; e < NE; e++) if (e != i1 && p[e] > m2) { m2 = p[e]; i2 = e; }
            float inv2 = 1.f / (m1 + m2);
            g_sel[tok][0] = i1; g_sel[tok][1] = i2;
            g_rw[tok][0] = m1 * inv2; g_rw[tok][1] = m2 * inv2;
            int tm = tmod[tok];
            int em0 = emod[i1], em1 = emod[i2];
            int fl = 0;
            if (tm != 0 && em0 != 0) { fl |= 1; if (tm * em0 == -1) fl |= 2; }
            if (tm != 0 && em1 != 0) { fl |= 4; if (tm * em1 == -1) fl |= 8; }
            g_flags[tok] = fl;
        }
        return;
    }

    // ---------------- prep role ----------------
    int pb = b - ROUTER_BLOCKS;        // 0 .. 3071
    __half* tileh = (__half*)smf;      // [64][72] transposed tile
    const float* src; __half* dst;
    int kt, nt, src_ld, dst_ld;
    if (pb < 2048) {
        int e = pb >> 8, rem = pb & 255;
        kt = (rem >> 4) * 64; nt = (rem & 15) * 64;
        src = gup + (size_t)e * HD * TWOF;  src_ld = TWOF;
        dst = &g_W1T[e][0][0];              dst_ld = HD;
    } else {
        int b2 = pb - 2048;
        int e = b2 >> 7, rem = b2 & 127;
        kt = (rem >> 4) * 64; nt = (rem & 15) * 64;
        src = down + (size_t)e * FF * HD;   src_ld = HD;
        dst = &g_W2T[e][0][0];              dst_ld = FF;
    }
    int n4 = t & 15, r4 = t >> 4;
    float4 v[4];
    #pragma unroll
    for (int i = 0; i < 4; i++)
        v[i] = *(const float4*)(src + (size_t)(kt + r4 * 4 + i) * src_ld + nt + n4 * 4);
    const float* fv = (const float*)v;
    #pragma unroll
    for (int j = 0; j < 4; j++) {
        __half hh[4];
        #pragma unroll
        for (int i = 0; i < 4; i++) hh[i] = __float2half_rn(fv[i * 4 + j]);
        *(uint2*)&tileh[(n4 * 4 + j) * 72 + r4 * 4] = *(const uint2*)hh;
    }
    __syncthreads();
    #pragma unroll
    for (int j = 0; j < 2; j++) {
        int idx = t + j * 256;
        int rw = idx >> 3, u = idx & 7;
        uint4 val = *(const uint4*)&tileh[rw * 72 + u * 8];
        *(uint4*)(dst + (size_t)(nt + rw) * dst_ld + kt + u * 8) = val;
    }
}

// ======================= K_assign2: single block — counts, skip, renorm, compaction ==========
__global__ void __launch_bounds__(512) k_assign2(const int* __restrict__ emod) {
    __shared__ int vcnt[NE], mcnt[NE], ecnt[NE];
    __shared__ int skip_s[NE];
    int t = threadIdx.x;
    if (t < NE) { vcnt[t] = 0; mcnt[t] = 0; ecnt[t] = 0; }
    __syncthreads();

    int flg[4], sel0[4], sel1[4];
    float w0a[4], w1a[4];
    #pragma unroll
    for (int i = 0; i < 4; i++) {
        int tok = t + i * 512;
        flg[i]  = g_flags[tok];
        sel0[i] = g_sel[tok][0]; sel1[i] = g_sel[tok][1];
        w0a[i]  = g_rw[tok][0];  w1a[i]  = g_rw[tok][1];
        if (flg[i] & 1) { atomicAdd(&vcnt[sel0[i]], 1); if (flg[i] & 2) atomicAdd(&mcnt[sel0[i]], 1); }
        if (flg[i] & 4) { atomicAdd(&vcnt[sel1[i]], 1); if (flg[i] & 8) atomicAdd(&mcnt[sel1[i]], 1); }
    }
    __syncthreads();
    if (t < NE) {
        int vc = vcnt[t], mc = mcnt[t];
        skip_s[t] = (vc > 0) && (mc == vc) && (emod[t] != 0);
    }
    __syncthreads();

    #pragma unroll
    for (int i = 0; i < 4; i++) {
        int tok = t + i * 512;
        float w0 = w0a[i], w1 = w1a[i];
        if (skip_s[sel0[i]]) w0 = 0.f;
        if (skip_s[sel1[i]]) w1 = 0.f;
        float sum = w0 + w1;
        if (sum > 0.f) { float inv = 1.f / fmaxf(sum, EPSV); w0 *= inv; w1 *= inv; }
        if (w0 > 0.f) {
            int p = atomicAdd(&ecnt[sel0[i]], 1);
            g_expert_tok[sel0[i]][p] = tok * 2;     g_expert_w[sel0[i]][p] = w0;
        }
        if (w1 > 0.f) {
            int p = atomicAdd(&ecnt[sel1[i]], 1);
            g_expert_tok[sel1[i]][p] = tok * 2 + 1; g_expert_w[sel1[i]][p] = w1;
        }
    }
    __syncthreads();
    if (t < NE) g_expert_cnt[t] = ecnt[t];
}

// ======================= K_mma1: GEMM1 fp16 + out zero-fill + SiLU*u, 3-stage ==============
#define ZO_F4 (BS * HD / 4)
__global__ void __launch_bounds__(256, 2) k_mma1(float4* __restrict__ out) {
    int e = blockIdx.z;
    int tid = threadIdx.x;

    // zero-fill out (grid-stride over full 1024-block grid; before any early exit)
    {
        unsigned bflat = (blockIdx.z * 16u + blockIdx.y) * 8u + blockIdx.x;  // 0..1023
        unsigned base = bflat * 512u + tid;                                  // 2 per thread
        out[base] = make_float4(0.f, 0.f, 0.f, 0.f);
        out[base + 256u] = make_float4(0.f, 0.f, 0.f, 0.f);
    }

    int count = g_expert_cnt[e];
    int m0 = blockIdx.y * 128;
    if (m0 >= count) return;
    int f0 = blockIdx.x * 64;

    extern __shared__ char sm[];
    unsigned sb = smem_u32(sm);
    int lane = tid & 31, w = tid >> 5;
    int wm = w & 3, wn = w >> 2;

    const __half* Xb = &g_xr[0][0];
    const __half* Wb = &g_W1T[e][0][0];
    const int* tokp = &g_expert_tok[e][0];

    unsigned ga_off[4]; const __half* gb[4]; unsigned soff[4];
    #pragma unroll
    for (int i = 0; i < 4; i++) {
        int idx = tid + i * 256;
        int r = idx >> 3, c = idx & 7;
        int s = m0 + r;
        int tok = (s < count) ? (tokp[s] >> 1) : 0;
        ga_off[i] = (unsigned)tok * HD + c * 8;
        int bh = r >> 6, l = r & 63;
        int col = f0 + bh * 32 + (l & 31);
        int rowg = col + ((l & 32) ? 512 : 0);
        gb[i] = Wb + (size_t)rowg * HD + c * 8;
        soff[i] = r * 128 + ((c ^ (r & 7)) << 4);
    }

    float acc[2][8][4];
    #pragma unroll
    for (int h = 0; h < 2; h++)
        #pragma unroll
        for (int f = 0; f < 8; f++)
            #pragma unroll
            for (int q = 0; q < 4; q++) acc[h][f][q] = 0.f;

    int l7 = lane & 7;
    int rA0 = (((lane >> 3) & 1) << 3) + l7;
    int cA  = lane >> 4;
    int rB0 = ((lane >> 4) << 3) + l7;
    int cB  = (lane >> 3) & 1;
    unsigned arow = (unsigned)(wm * 32 + rA0) * 128;
    unsigned brow0 = (unsigned)(wn * 64 + rB0) * 128;

    const int NK = HD / 64;
    #pragma unroll
    for (int i = 0; i < 4; i++) {
        CP16(sb + SMH_A(0) + soff[i], Xb + ga_off[i]);
        CP16(sb + SMH_B(0) + soff[i], gb[i]);
    }
    CPCOMMIT();
    #pragma unroll
    for (int i = 0; i < 4; i++) {
        CP16(sb + SMH_A(1) + soff[i], Xb + ga_off[i] + 64);
        CP16(sb + SMH_B(1) + soff[i], gb[i] + 64);
    }
    CPCOMMIT();

    for (int kb = 0; kb < NK; kb++) {
        int s = kb % 3;
        if (kb >= NK - 1) { CPWAIT(0); } else { CPWAIT(1); }
        __syncthreads();
        if (kb + 2 < NK) {
            int ns = (kb + 2) % 3;
            #pragma unroll
            for (int i = 0; i < 4; i++) {
                CP16(sb + SMH_A(ns) + soff[i], Xb + ga_off[i] + (kb + 2) * 64);
                CP16(sb + SMH_B(ns) + soff[i], gb[i] + (kb + 2) * 64);
            }
            CPCOMMIT();
        }
        unsigned sA = sb + SMH_A(s) + arow;
        unsigned sB = sb + SMH_B(s) + brow0;
        #pragma unroll
        for (int kc = 0; kc < 4; kc++) {
            unsigned aoff = (unsigned)(((kc * 2 + cA) ^ l7) << 4);
            unsigned boff = (unsigned)(((kc * 2 + cB) ^ l7) << 4);
            unsigned a0, a1, a2, a3, a4, a5, a6, a7;
            LDSM4(a0, a1, a2, a3, sA + aoff);
            LDSM4(a4, a5, a6, a7, sA + 2048 + aoff);
            #pragma unroll
            for (int fg = 0; fg < 4; fg++) {
                unsigned b0, b1, b2, b3;
                LDSM4(b0, b1, b2, b3, sB + fg * 2048 + boff);
                MMAH(acc[0][2 * fg],     a0, a1, a2, a3, b0, b1);
                MMAH(acc[0][2 * fg + 1], a0, a1, a2, a3, b2, b3);
                MMAH(acc[1][2 * fg],     a4, a5, a6, a7, b0, b1);
                MMAH(acc[1][2 * fg + 1], a4, a5, a6, a7, b2, b3);
            }
        }
    }

    int p = lane & 3, rlo = lane >> 2;
    #pragma unroll
    for (int h = 0; h < 2; h++) {
        int slot0 = m0 + wm * 32 + h * 16 + rlo;
        int slot1 = slot0 + 8;
        #pragma unroll
        for (int f = 0; f < 4; f++) {
            int j = f0 + wn * 32 + f * 8 + 2 * p;
            if (slot0 < count) {
                float g0 = acc[h][f][0], g1 = acc[h][f][1];
                float u0 = acc[h][f + 4][0], u1 = acc[h][f + 4][1];
                float v0 = g0 / (1.f + __expf(-g0)) * u0;
                float v1 = g1 / (1.f + __expf(-g1)) * u1;
                *(__half2*)&g_act[e][slot0][j] = __floats2half2_rn(v0, v1);
            }
            if (slot1 < count) {
                float g0 = acc[h][f][2], g1 = acc[h][f][3];
                float u0 = acc[h][f + 4][2], u1 = acc[h][f + 4][3];
                float v0 = g0 / (1.f + __expf(-g0)) * u0;
                float v1 = g1 / (1.f + __expf(-g1)) * u1;
                *(__half2*)&g_act[e][slot1][j] = __floats2half2_rn(v0, v1);
            }
        }
    }
}

// ======================= K_mma2: GEMM2 fp16, 3-stage, v2-red accumulate ==========
__global__ void __launch_bounds__(256, 2) k_mma2(float* __restrict__ out) {
    int e = blockIdx.z;
    int count = g_expert_cnt[e];
    int m0 = blockIdx.y * 128;
    if (m0 >= count) return;
    int n0 = blockIdx.x * 128;

    extern __shared__ char sm[];
    unsigned sb = smem_u32(sm);
    int tid = threadIdx.x, lane = tid & 31, w = tid >> 5;
    int wm = w & 3, wn = w >> 2;

    const __half* Ab = &g_act[e][m0][0];
    const __half* Wb = &g_W2T[e][n0][0];

    const __half* ga[4]; const __half* gb[4]; unsigned soff[4];
    #pragma unroll
    for (int i = 0; i < 4; i++) {
        int idx = tid + i * 256;
        int r = idx >> 3, c = idx & 7;
        ga[i] = Ab + (size_t)r * FF + c * 8;
        gb[i] = Wb + (size_t)r * FF + c * 8;
        soff[i] = r * 128 + ((c ^ (r & 7)) << 4);
    }

    // issue first two stages BEFORE the tsp/tw smem fill (no barrier needed here:
    // the first mainloop __syncthreads orders the smem writes before any read)
    const int NK = FF / 64;
    #pragma unroll
    for (int i = 0; i < 4; i++) {
        CP16(sb + SMH_A(0) + soff[i], ga[i]);
        CP16(sb + SMH_B(0) + soff[i], gb[i]);
    }
    CPCOMMIT();
    #pragma unroll
    for (int i = 0; i < 4; i++) {
        CP16(sb + SMH_A(1) + soff[i], ga[i] + 64);
        CP16(sb + SMH_B(1) + soff[i], gb[i] + 64);
    }
    CPCOMMIT();

    int*   tsp = (int*)sm;
    float* tw  = (float*)(sm + 512);
    if (tid < 128) {
        int s = m0 + tid;
        tsp[tid] = (s < count) ? g_expert_tok[e][s] : -1;
        tw[tid]  = (s < count) ? g_expert_w[e][s] : 0.f;
    }

    float acc[2][8][4];
    #pragma unroll
    for (int h = 0; h < 2; h++)
        #pragma unroll
        for (int f = 0; f < 8; f++)
            #pragma unroll
            for (int q = 0; q < 4; q++) acc[h][f][q] = 0.f;

    int l7 = lane & 7;
    int rA0 = (((lane >> 3) & 1) << 3) + l7;
    int cA  = lane >> 4;
    int rB0 = ((lane >> 4) << 3) + l7;
    int cB  = (lane >> 3) & 1;
    unsigned arow = (unsigned)(wm * 32 + rA0) * 128;
    unsigned brow0 = (unsigned)(wn * 64 + rB0) * 128;

    for (int kb = 0; kb < NK; kb++) {
        int s = kb % 3;
        if (kb >= NK - 1) { CPWAIT(0); } else { CPWAIT(1); }
        __syncthreads();
        if (kb + 2 < NK) {
            int ns = (kb + 2) % 3;
            #pragma unroll
            for (int i = 0; i < 4; i++) {
                CP16(sb + SMH_A(ns) + soff[i], ga[i] + (kb + 2) * 64);
                CP16(sb + SMH_B(ns) + soff[i], gb[i] + (kb + 2) * 64);
            }
            CPCOMMIT();
        }
        unsigned sA = sb + SMH_A(s) + arow;
        unsigned sB = sb + SMH_B(s) + brow0;
        #pragma unroll
        for (int kc = 0; kc < 4; kc++) {
            unsigned aoff = (unsigned)(((kc * 2 + cA) ^ l7) << 4);
            unsigned boff = (unsigned)(((kc * 2 + cB) ^ l7) << 4);
            unsigned a0, a1, a2, a3, a4, a5, a6, a7;
            LDSM4(a0, a1, a2, a3, sA + aoff);
            LDSM4(a4, a5, a6, a7, sA + 2048 + aoff);
            #pragma unroll
            for (int fg = 0; fg < 4; fg++) {
                unsigned b0, b1, b2, b3;
                LDSM4(b0, b1, b2, b3, sB + fg * 2048 + boff);
                MMAH(acc[0][2 * fg],     a0, a1, a2, a3, b0, b1);
                MMAH(acc[0][2 * fg + 1], a0, a1, a2, a3, b2, b3);
                MMAH(acc[1][2 * fg],     a4, a5, a6, a7, b0, b1);
                MMAH(acc[1][2 * fg + 1], a4, a5, a6, a7, b2, b3);
            }
        }
    }

    // epilogue: weighted v2 reductions into out (pre-zeroed by k_mma1; <=2 adds/address)
    int p = lane & 3, rlo = lane >> 2;
    #pragma unroll
    for (int h = 0; h < 2; h++) {
        int r0i = wm * 32 + h * 16 + rlo;
        int r1i = r0i + 8;
        int pk0 = tsp[r0i], pk1 = tsp[r1i];
        float wt0 = tw[r0i], wt1 = tw[r1i];
        #pragma unroll
        for (int f = 0; f < 8; f++) {
            int j = n0 + wn * 64 + f * 8 + 2 * p;
            if (pk0 >= 0) {
                float* dst = out + (size_t)(pk0 >> 1) * HD + j;
                REDV2(dst, acc[h][f][0] * wt0, acc[h][f][1] * wt0);
            }
            if (pk1 >= 0) {
                float* dst = out + (size_t)(pk1 >> 1) * HD + j;
                REDV2(dst, acc[h][f][2] * wt1, acc[h][f][3] * wt1);
            }
        }
    }
}

// ======================= launch =======================
extern "C" void kernel_launch(void* const* d_in, const int* in_sizes, int n_in,
                              void* d_out, int out_size)
{
    const float* x    = (const float*)d_in[0];
    const float* gw   = (const float*)d_in[1];
    const float* gup  = (const float*)d_in[2];
    const float* down = (const float*)d_in[3];
    const int*   tmod = (const int*)d_in[4];
    const int*   emod = (const int*)d_in[5];
    float* out = (float*)d_out;

    cudaFuncSetAttribute(k_mma1, cudaFuncAttributeMaxDynamicSharedMemorySize, SMH_BYTES);
    cudaFuncSetAttribute(k_mma2, cudaFuncAttributeMaxDynamicSharedMemorySize, SMH_BYTES);

    k_fused<<<FUSED_BLOCKS, 256>>>(gup, down, x, gw, tmod, emod);
    k_assign2<<<1, 512>>>(emod);
    k_mma1<<<dim3(8, 16, NE), 256, SMH_BYTES>>>((float4*)out);
    k_mma2<<<dim3(8, 16, NE), 256, SMH_BYTES>>>(out);
}